// round 2
// baseline (speedup 1.0000x reference)
#include <cuda_runtime.h>
#include <cuda_bf16.h>
#include <math.h>

// ---------------- problem constants ----------------
#define DD      128      // node feature dim
#define HH      256      // hidden = 2*D
#define MAXN    8192
#define NB      64       // batches
#define RP      132      // padded row stride for Ht (256 x 132 floats)

// scratch (global __device__ arrays: sanctioned, no cudaMalloc)
__device__ float g_messages[2ull * MAXN * HH];   // 16 MB
__device__ float g_att[2ull * MAXN * DD];        // 8 MB
__device__ float g_colmeans[2 * DD];
__device__ int   g_seg[2 * NB * 2];

// shared memory layout for the fused MLP kernels
#define SMEM_FLOATS (256*RP + 16*128 + 16*128)
#define SMEM_BYTES  (SMEM_FLOATS*4 + 256*4)

// ---------------- tiny setup kernels ----------------
__global__ void zero_msgs_kernel(int n) {
    int i = blockIdx.x * blockDim.x + threadIdx.x;
    if (i < n) g_messages[i] = 0.f;
}

__global__ void seg_kernel(const int* __restrict__ b1,
                           const int* __restrict__ b2, int N) {
    int t = threadIdx.x;
    if (t >= 2 * NB) return;
    int g = t / NB;
    int b = t % NB;
    const int* arr = g ? b2 : b1;
    int lo = 0, hi = N;
    while (lo < hi) { int mid = (lo + hi) >> 1; if (arr[mid] < b) lo = mid + 1; else hi = mid; }
    int start = lo;
    lo = 0; hi = N;
    while (lo < hi) { int mid = (lo + hi) >> 1; if (arr[mid] <= b) lo = mid + 1; else hi = mid; }
    g_seg[t * 2 + 0] = start;
    g_seg[t * 2 + 1] = lo;
}

__global__ void colmean_kernel(const float* __restrict__ x1,
                               const float* __restrict__ x2, int N) {
    const float* x = blockIdx.x ? x2 : x1;
    int c = threadIdx.x;   // 0..127
    float s0 = 0.f, s1 = 0.f, s2 = 0.f, s3 = 0.f;
    int r = 0;
    for (; r + 3 < N; r += 4) {
        s0 += x[(size_t)(r + 0) * DD + c];
        s1 += x[(size_t)(r + 1) * DD + c];
        s2 += x[(size_t)(r + 2) * DD + c];
        s3 += x[(size_t)(r + 3) * DD + c];
    }
    for (; r < N; ++r) s0 += x[(size_t)r * DD + c];
    g_colmeans[blockIdx.x * DD + c] = (s0 + s1 + s2 + s3) * (1.f / (float)N);
}

// ---------------- fused message MLP + scatter ----------------
// per CTA: 128 edges. Stage A: H = relu([x[src],x[tgt]] @ W1 + b1)  (128x256)
//          Stage B: M = H @ W2 + b2 ; atomicAdd into messages[tgt]
__global__ void __launch_bounds__(256, 1)
msg_kernel(const float* __restrict__ x1, const float* __restrict__ x2,
           const int* __restrict__ ei1, const int* __restrict__ ei2,
           const float* __restrict__ W1, const float* __restrict__ b1,
           const float* __restrict__ W2, const float* __restrict__ b2,
           int N, int E) {
    int g = blockIdx.y;
    const float* x = g ? x2 : x1;
    const int* ei = g ? ei2 : ei1;
    float* messages = g_messages + (size_t)g * N * HH;

    extern __shared__ float sm[];
    float* Ht = sm;                       // [256][RP]
    float* As = Ht + 256 * RP;            // [16][128]
    float* Ws = As + 16 * 128;            // [16][128]
    int*   s_src = (int*)(Ws + 16 * 128); // [128]
    int*   s_tgt = s_src + 128;

    int tid = threadIdx.x;
    int base = blockIdx.x * 128;

    if (tid < 128) {
        int e = base + tid;
        s_tgt[tid] = (e < E) ? ei[e] : 0;
        s_src[tid] = (e < E) ? ei[E + e] : 0;
    }
    __syncthreads();

    int ty = tid >> 4, tx = tid & 15;
    int lr = tid >> 1, lk0 = (tid & 1) * 8;   // A-tile loader
    int wk = tid >> 4, wc = (tid & 15) * 8;   // W-tile loader

    // ---------- stage A ----------
    for (int nh = 0; nh < 2; ++nh) {
        float c[8][8];
        #pragma unroll
        for (int i = 0; i < 8; i++)
            #pragma unroll
            for (int j = 0; j < 8; j++) c[i][j] = 0.f;

        for (int kt = 0; kt < 16; ++kt) {
            // gathered A tile: A[r][kk], kk<128 -> x[src], else x[tgt]
            {
                int kk = kt * 16 + lk0;
                int node = (kk < 128) ? s_src[lr] : s_tgt[lr];
                const float4* p = (const float4*)(x + (size_t)node * DD + (kk & 127));
                float4 v0 = p[0], v1 = p[1];
                As[(lk0 + 0) * 128 + lr] = v0.x;
                As[(lk0 + 1) * 128 + lr] = v0.y;
                As[(lk0 + 2) * 128 + lr] = v0.z;
                As[(lk0 + 3) * 128 + lr] = v0.w;
                As[(lk0 + 4) * 128 + lr] = v1.x;
                As[(lk0 + 5) * 128 + lr] = v1.y;
                As[(lk0 + 6) * 128 + lr] = v1.z;
                As[(lk0 + 7) * 128 + lr] = v1.w;
            }
            {
                const float4* p = (const float4*)(W1 + (size_t)(kt * 16 + wk) * HH + nh * 128 + wc);
                float4 v0 = p[0], v1 = p[1];
                *(float4*)(Ws + wk * 128 + wc) = v0;
                *(float4*)(Ws + wk * 128 + wc + 4) = v1;
            }
            __syncthreads();
            #pragma unroll
            for (int k = 0; k < 16; ++k) {
                float a[8], b[8];
                float4 t0 = *(const float4*)(As + k * 128 + ty * 8);
                float4 t1 = *(const float4*)(As + k * 128 + ty * 8 + 4);
                a[0]=t0.x; a[1]=t0.y; a[2]=t0.z; a[3]=t0.w;
                a[4]=t1.x; a[5]=t1.y; a[6]=t1.z; a[7]=t1.w;
                float4 u0 = *(const float4*)(Ws + k * 128 + tx * 8);
                float4 u1 = *(const float4*)(Ws + k * 128 + tx * 8 + 4);
                b[0]=u0.x; b[1]=u0.y; b[2]=u0.z; b[3]=u0.w;
                b[4]=u1.x; b[5]=u1.y; b[6]=u1.z; b[7]=u1.w;
                #pragma unroll
                for (int i = 0; i < 8; i++)
                    #pragma unroll
                    for (int j = 0; j < 8; j++)
                        c[i][j] = fmaf(a[i], b[j], c[i][j]);
            }
            __syncthreads();
        }
        // epilogue: bias + relu -> Ht[n][r]
        #pragma unroll
        for (int j = 0; j < 8; j++) {
            int n = nh * 128 + tx * 8 + j;
            float bj = b1[n];
            #pragma unroll
            for (int i = 0; i < 8; i++) {
                float v = c[i][j] + bj;
                Ht[n * RP + ty * 8 + i] = v > 0.f ? v : 0.f;
            }
        }
        __syncthreads();
    }

    // ---------- stage B ----------
    for (int nh = 0; nh < 2; ++nh) {
        float c[8][8];
        #pragma unroll
        for (int i = 0; i < 8; i++)
            #pragma unroll
            for (int j = 0; j < 8; j++) c[i][j] = 0.f;

        for (int kt = 0; kt < 16; ++kt) {
            {
                const float4* p = (const float4*)(W2 + (size_t)(kt * 16 + wk) * HH + nh * 128 + wc);
                float4 v0 = p[0], v1 = p[1];
                *(float4*)(Ws + wk * 128 + wc) = v0;
                *(float4*)(Ws + wk * 128 + wc + 4) = v1;
            }
            __syncthreads();
            #pragma unroll
            for (int k = 0; k < 16; ++k) {
                int kk = kt * 16 + k;
                float a[8], b[8];
                float4 t0 = *(const float4*)(Ht + kk * RP + ty * 8);
                float4 t1 = *(const float4*)(Ht + kk * RP + ty * 8 + 4);
                a[0]=t0.x; a[1]=t0.y; a[2]=t0.z; a[3]=t0.w;
                a[4]=t1.x; a[5]=t1.y; a[6]=t1.z; a[7]=t1.w;
                float4 u0 = *(const float4*)(Ws + k * 128 + tx * 8);
                float4 u1 = *(const float4*)(Ws + k * 128 + tx * 8 + 4);
                b[0]=u0.x; b[1]=u0.y; b[2]=u0.z; b[3]=u0.w;
                b[4]=u1.x; b[5]=u1.y; b[6]=u1.z; b[7]=u1.w;
                #pragma unroll
                for (int i = 0; i < 8; i++)
                    #pragma unroll
                    for (int j = 0; j < 8; j++)
                        c[i][j] = fmaf(a[i], b[j], c[i][j]);
            }
            __syncthreads();
        }
        // epilogue: scatter-add into messages[tgt]
        #pragma unroll
        for (int i = 0; i < 8; i++) {
            int r = ty * 8 + i;
            if (base + r < E) {
                int node = s_tgt[r];
                float* mrow = messages + (size_t)node * HH + nh * 128 + tx * 8;
                #pragma unroll
                for (int j = 0; j < 8; j++)
                    atomicAdd(mrow + j, c[i][j] + b2[nh * 128 + tx * 8 + j]);
            }
        }
        __syncthreads();
    }
}

// ---------------- block-diagonal cross attention ----------------
__global__ void attn_kernel(const float* __restrict__ x1,
                            const float* __restrict__ x2, int N) {
    int b = blockIdx.x;
    int dir = blockIdx.y;
    const float* rowsrc = dir ? x2 : x1;
    const float* colsrc = dir ? x1 : x2;
    float* att = g_att + (size_t)dir * N * DD;
    int rs = g_seg[(dir * NB + b) * 2 + 0];
    int re = g_seg[(dir * NB + b) * 2 + 1];
    int cs = g_seg[((1 - dir) * NB + b) * 2 + 0];
    int ce = g_seg[((1 - dir) * NB + b) * 2 + 1];
    const float* mean = g_colmeans + (1 - dir) * DD;

    int warp = threadIdx.x >> 5, lane = threadIdx.x & 31;

    for (int i = rs + warp; i < re; i += 8) {
        float4 a = *(const float4*)(rowsrc + (size_t)i * DD + lane * 4);
        float4 res;
        if (cs == ce) {
            // empty opposite batch: reference softmax is uniform over ALL nodes
            float4 mv = *(const float4*)(mean + lane * 4);
            res.x = a.x - mv.x; res.y = a.y - mv.y;
            res.z = a.z - mv.z; res.w = a.w - mv.w;
        } else {
            float m = -3.4e38f;
            for (int j = cs; j < ce; ++j) {
                float4 bv = *(const float4*)(colsrc + (size_t)j * DD + lane * 4);
                float d = a.x * bv.x + a.y * bv.y + a.z * bv.z + a.w * bv.w;
                #pragma unroll
                for (int o = 16; o; o >>= 1) d += __shfl_xor_sync(0xffffffffu, d, o);
                m = fmaxf(m, d);
            }
            float se = 0.f;
            float4 acc = make_float4(0.f, 0.f, 0.f, 0.f);
            for (int j = cs; j < ce; ++j) {
                float4 bv = *(const float4*)(colsrc + (size_t)j * DD + lane * 4);
                float d = a.x * bv.x + a.y * bv.y + a.z * bv.z + a.w * bv.w;
                #pragma unroll
                for (int o = 16; o; o >>= 1) d += __shfl_xor_sync(0xffffffffu, d, o);
                float w = __expf(d - m);
                se += w;
                acc.x = fmaf(w, bv.x, acc.x);
                acc.y = fmaf(w, bv.y, acc.y);
                acc.z = fmaf(w, bv.z, acc.z);
                acc.w = fmaf(w, bv.w, acc.w);
            }
            float inv = 1.f / se;
            res.x = a.x - acc.x * inv; res.y = a.y - acc.y * inv;
            res.z = a.z - acc.z * inv; res.w = a.w - acc.w * inv;
        }
        *(float4*)(att + (size_t)i * DD + lane * 4) = res;
    }
}

// ---------------- fused node update MLP ----------------
// u = [messages(256) | att(128) | x(128)]  (K=512)
// H = relu(u @ W1u + b1u) (128x256); out = x + H @ W2u + b2u (128x128)
__global__ void __launch_bounds__(256, 1)
upd_kernel(const float* __restrict__ x1, const float* __restrict__ x2,
           const float* __restrict__ W1u, const float* __restrict__ b1u,
           const float* __restrict__ W2u, const float* __restrict__ b2u,
           float* __restrict__ out, int N) {
    int g = blockIdx.y;
    const float* x = g ? x2 : x1;
    const float* messages = g_messages + (size_t)g * N * HH;
    const float* att = g_att + (size_t)g * N * DD;
    float* o = out + (size_t)g * N * DD;

    extern __shared__ float sm[];
    float* Ht = sm;
    float* As = Ht + 256 * RP;
    float* Ws = As + 16 * 128;

    int tid = threadIdx.x;
    int base = blockIdx.x * 128;
    int ty = tid >> 4, tx = tid & 15;
    int lr = tid >> 1, lk0 = (tid & 1) * 8;
    int wk = tid >> 4, wc = (tid & 15) * 8;

    int mynode = base + lr;
    if (mynode >= N) mynode = N - 1;

    // ---------- stage 1: K = 512 ----------
    for (int nh = 0; nh < 2; ++nh) {
        float c[8][8];
        #pragma unroll
        for (int i = 0; i < 8; i++)
            #pragma unroll
            for (int j = 0; j < 8; j++) c[i][j] = 0.f;

        for (int kt = 0; kt < 32; ++kt) {
            {
                int kk = kt * 16 + lk0;
                const float* src;
                int col;
                if (kk < 256)      { src = messages + (size_t)mynode * HH; col = kk; }
                else if (kk < 384) { src = att + (size_t)mynode * DD;      col = kk - 256; }
                else               { src = x + (size_t)mynode * DD;        col = kk - 384; }
                const float4* p = (const float4*)(src + col);
                float4 v0 = p[0], v1 = p[1];
                As[(lk0 + 0) * 128 + lr] = v0.x;
                As[(lk0 + 1) * 128 + lr] = v0.y;
                As[(lk0 + 2) * 128 + lr] = v0.z;
                As[(lk0 + 3) * 128 + lr] = v0.w;
                As[(lk0 + 4) * 128 + lr] = v1.x;
                As[(lk0 + 5) * 128 + lr] = v1.y;
                As[(lk0 + 6) * 128 + lr] = v1.z;
                As[(lk0 + 7) * 128 + lr] = v1.w;
            }
            {
                const float4* p = (const float4*)(W1u + (size_t)(kt * 16 + wk) * HH + nh * 128 + wc);
                float4 v0 = p[0], v1 = p[1];
                *(float4*)(Ws + wk * 128 + wc) = v0;
                *(float4*)(Ws + wk * 128 + wc + 4) = v1;
            }
            __syncthreads();
            #pragma unroll
            for (int k = 0; k < 16; ++k) {
                float a[8], b[8];
                float4 t0 = *(const float4*)(As + k * 128 + ty * 8);
                float4 t1 = *(const float4*)(As + k * 128 + ty * 8 + 4);
                a[0]=t0.x; a[1]=t0.y; a[2]=t0.z; a[3]=t0.w;
                a[4]=t1.x; a[5]=t1.y; a[6]=t1.z; a[7]=t1.w;
                float4 u0 = *(const float4*)(Ws + k * 128 + tx * 8);
                float4 u1 = *(const float4*)(Ws + k * 128 + tx * 8 + 4);
                b[0]=u0.x; b[1]=u0.y; b[2]=u0.z; b[3]=u0.w;
                b[4]=u1.x; b[5]=u1.y; b[6]=u1.z; b[7]=u1.w;
                #pragma unroll
                for (int i = 0; i < 8; i++)
                    #pragma unroll
                    for (int j = 0; j < 8; j++)
                        c[i][j] = fmaf(a[i], b[j], c[i][j]);
            }
            __syncthreads();
        }
        #pragma unroll
        for (int j = 0; j < 8; j++) {
            int n = nh * 128 + tx * 8 + j;
            float bj = b1u[n];
            #pragma unroll
            for (int i = 0; i < 8; i++) {
                float v = c[i][j] + bj;
                Ht[n * RP + ty * 8 + i] = v > 0.f ? v : 0.f;
            }
        }
        __syncthreads();
    }

    // ---------- stage 2: 128x128 = Ht(128x256) @ W2u(256x128) ----------
    {
        float c[8][8];
        #pragma unroll
        for (int i = 0; i < 8; i++)
            #pragma unroll
            for (int j = 0; j < 8; j++) c[i][j] = 0.f;

        for (int kt = 0; kt < 16; ++kt) {
            {
                const float4* p = (const float4*)(W2u + (size_t)(kt * 16 + wk) * DD + wc);
                float4 v0 = p[0], v1 = p[1];
                *(float4*)(Ws + wk * 128 + wc) = v0;
                *(float4*)(Ws + wk * 128 + wc + 4) = v1;
            }
            __syncthreads();
            #pragma unroll
            for (int k = 0; k < 16; ++k) {
                int kk = kt * 16 + k;
                float a[8], b[8];
                float4 t0 = *(const float4*)(Ht + kk * RP + ty * 8);
                float4 t1 = *(const float4*)(Ht + kk * RP + ty * 8 + 4);
                a[0]=t0.x; a[1]=t0.y; a[2]=t0.z; a[3]=t0.w;
                a[4]=t1.x; a[5]=t1.y; a[6]=t1.z; a[7]=t1.w;
                float4 u0 = *(const float4*)(Ws + k * 128 + tx * 8);
                float4 u1 = *(const float4*)(Ws + k * 128 + tx * 8 + 4);
                b[0]=u0.x; b[1]=u0.y; b[2]=u0.z; b[3]=u0.w;
                b[4]=u1.x; b[5]=u1.y; b[6]=u1.z; b[7]=u1.w;
                #pragma unroll
                for (int i = 0; i < 8; i++)
                    #pragma unroll
                    for (int j = 0; j < 8; j++)
                        c[i][j] = fmaf(a[i], b[j], c[i][j]);
            }
            __syncthreads();
        }
        #pragma unroll
        for (int i = 0; i < 8; i++) {
            int node = base + ty * 8 + i;
            if (node < N) {
                int col = tx * 8;
                #pragma unroll
                for (int j = 0; j < 8; j++) {
                    float v = c[i][j] + b2u[col + j] + x[(size_t)node * DD + col + j];
                    o[(size_t)node * DD + col + j] = v;
                }
            }
        }
    }
}

// ---------------- launcher ----------------
extern "C" void kernel_launch(void* const* d_in, const int* in_sizes, int n_in,
                              void* d_out, int out_size) {
    const float* x1   = (const float*)d_in[0];
    const int*   ei1  = (const int*)d_in[1];
    const int*   bat1 = (const int*)d_in[2];
    const float* x2   = (const float*)d_in[3];
    const int*   ei2  = (const int*)d_in[4];
    const int*   bat2 = (const int*)d_in[5];
    const float* mW1 = (const float*)d_in[6];
    const float* mb1 = (const float*)d_in[7];
    const float* mW2 = (const float*)d_in[8];
    const float* mb2 = (const float*)d_in[9];
    const float* uW1 = (const float*)d_in[10];
    const float* ub1 = (const float*)d_in[11];
    const float* uW2 = (const float*)d_in[12];
    const float* ub2 = (const float*)d_in[13];
    float* out = (float*)d_out;

    int N = in_sizes[2];          // nodes per graph
    int E = in_sizes[1] / 2;      // edges per graph

    cudaFuncSetAttribute(msg_kernel, cudaFuncAttributeMaxDynamicSharedMemorySize, SMEM_BYTES);
    cudaFuncSetAttribute(upd_kernel, cudaFuncAttributeMaxDynamicSharedMemorySize, SMEM_BYTES);

    int zn = 2 * N * HH;
    zero_msgs_kernel<<<(zn + 255) / 256, 256>>>(zn);
    seg_kernel<<<1, 128>>>(bat1, bat2, N);
    colmean_kernel<<<2, DD>>>(x1, x2, N);

    dim3 mgrid((E + 127) / 128, 2);
    msg_kernel<<<mgrid, 256, SMEM_BYTES>>>(x1, x2, ei1, ei2, mW1, mb1, mW2, mb2, N, E);

    attn_kernel<<<dim3(NB, 2), 256>>>(x1, x2, N);

    dim3 ugrid((N + 127) / 128, 2);
    upd_kernel<<<ugrid, 256, SMEM_BYTES>>>(x1, x2, uW1, ub1, uW2, ub2, out, N);
}

// round 3
// speedup vs baseline: 1.0947x; 1.0947x over previous
#include <cuda_runtime.h>
#include <cuda_bf16.h>
#include <math.h>

// ---------------- problem constants ----------------
#define DD      128      // node feature dim
#define HH      256      // hidden = 2*D
#define MAXN    8192
#define NB      64       // batches
#define RP      132      // padded row stride for Ht (256 x 132 floats)

// scratch (global __device__ arrays: sanctioned, no cudaMalloc)
__device__ float g_messages[2ull * MAXN * HH];   // 16 MB
__device__ float g_att[2ull * MAXN * DD];        // 8 MB
__device__ float g_colmeans[2 * DD];
__device__ int   g_seg[2 * NB * 2];

// shared memory layout for the fused MLP kernels:
// Ht: 256*RP floats, As: 2 x 16*128, Ws: 2 x 16*128, ids: 256 ints
#define TILE_F   (16*128)
#define SMEM_FLOATS (256*RP + 2*TILE_F + 2*TILE_F)
#define SMEM_BYTES  (SMEM_FLOATS*4 + 256*4)

// ---------------- tiny setup kernels ----------------
__global__ void zero_msgs_kernel(int n) {
    int i = blockIdx.x * blockDim.x + threadIdx.x;
    if (i < n) g_messages[i] = 0.f;
}

__global__ void seg_kernel(const int* __restrict__ b1,
                           const int* __restrict__ b2, int N) {
    int t = threadIdx.x;
    if (t >= 2 * NB) return;
    int g = t / NB;
    int b = t % NB;
    const int* arr = g ? b2 : b1;
    int lo = 0, hi = N;
    while (lo < hi) { int mid = (lo + hi) >> 1; if (arr[mid] < b) lo = mid + 1; else hi = mid; }
    int start = lo;
    lo = 0; hi = N;
    while (lo < hi) { int mid = (lo + hi) >> 1; if (arr[mid] <= b) lo = mid + 1; else hi = mid; }
    g_seg[t * 2 + 0] = start;
    g_seg[t * 2 + 1] = lo;
}

__global__ void colmean_kernel(const float* __restrict__ x1,
                               const float* __restrict__ x2, int N) {
    const float* x = blockIdx.x ? x2 : x1;
    int c = threadIdx.x;   // 0..127
    float s0 = 0.f, s1 = 0.f, s2 = 0.f, s3 = 0.f;
    int r = 0;
    for (; r + 3 < N; r += 4) {
        s0 += x[(size_t)(r + 0) * DD + c];
        s1 += x[(size_t)(r + 1) * DD + c];
        s2 += x[(size_t)(r + 2) * DD + c];
        s3 += x[(size_t)(r + 3) * DD + c];
    }
    for (; r < N; ++r) s0 += x[(size_t)r * DD + c];
    g_colmeans[blockIdx.x * DD + c] = (s0 + s1 + s2 + s3) * (1.f / (float)N);
}

// ---------------- f32x2 micro-kernel ----------------
// A tile: [16][128] k-major (row stride astride floats)
// W tile: [16][128] split-half layout: Wtile[k*128 + h*64 + tx*4 + q]
//         holds original col (tx*8 + h*4 + q) -> thread tx owns cols tx*8..+7
// c2[i][j] accumulates packed (cols 2j, 2j+1) of this thread's 8-col block
__device__ __forceinline__ void mma16_f32x2(
    const float* __restrict__ Atile, int astride,
    const float* __restrict__ Wtile,
    int ty, int tx, unsigned long long c2[8][4])
{
    #pragma unroll
    for (int k = 0; k < 16; ++k) {
        float4 t0 = *(const float4*)(Atile + k * astride + ty * 8);
        float4 t1 = *(const float4*)(Atile + k * astride + ty * 8 + 4);
        ulonglong2 u0 = *(const ulonglong2*)(Wtile + k * 128 + tx * 4);
        ulonglong2 u1 = *(const ulonglong2*)(Wtile + k * 128 + 64 + tx * 4);
        unsigned long long b2[4];
        b2[0] = u0.x; b2[1] = u0.y; b2[2] = u1.x; b2[3] = u1.y;
        unsigned int ar[8];
        ar[0]=__float_as_uint(t0.x); ar[1]=__float_as_uint(t0.y);
        ar[2]=__float_as_uint(t0.z); ar[3]=__float_as_uint(t0.w);
        ar[4]=__float_as_uint(t1.x); ar[5]=__float_as_uint(t1.y);
        ar[6]=__float_as_uint(t1.z); ar[7]=__float_as_uint(t1.w);
        unsigned long long a2[8];
        #pragma unroll
        for (int i = 0; i < 8; i++)
            asm("mov.b64 %0, {%1, %1};" : "=l"(a2[i]) : "r"(ar[i]));
        #pragma unroll
        for (int i = 0; i < 8; i++)
            #pragma unroll
            for (int j = 0; j < 4; j++)
                asm("fma.rn.f32x2 %0, %1, %2, %0;"
                    : "+l"(c2[i][j]) : "l"(a2[i]), "l"(b2[j]));
    }
}

__device__ __forceinline__ void unpack2(unsigned long long v, float& lo, float& hi) {
    unsigned int l, h;
    asm("mov.b64 {%0, %1}, %2;" : "=r"(l), "=r"(h) : "l"(v));
    lo = __uint_as_float(l); hi = __uint_as_float(h);
}

// store a W row-fragment (8 floats v0,v1 for cols w16*8..+7) into split layout
__device__ __forceinline__ void sts_w(float* Wbuf, int wk, int w16, float4 v0, float4 v1) {
    *(float4*)(Wbuf + wk * 128 + w16 * 4) = v0;
    *(float4*)(Wbuf + wk * 128 + 64 + w16 * 4) = v1;
}

// ---------------- fused message MLP + scatter ----------------
__global__ void __launch_bounds__(256, 1)
msg_kernel(const float* __restrict__ x1, const float* __restrict__ x2,
           const int* __restrict__ ei1, const int* __restrict__ ei2,
           const float* __restrict__ W1, const float* __restrict__ b1,
           const float* __restrict__ W2, const float* __restrict__ b2,
           int N, int E) {
    int g = blockIdx.y;
    const float* x = g ? x2 : x1;
    const int* ei = g ? ei2 : ei1;
    float* messages = g_messages + (size_t)g * N * HH;

    extern __shared__ float sm[];
    float* Ht = sm;                        // [256][RP]
    float* As = Ht + 256 * RP;             // [2][16*128]
    float* Ws = As + 2 * TILE_F;           // [2][16*128]
    int*   s_src = (int*)(Ws + 2 * TILE_F);
    int*   s_tgt = s_src + 128;

    int tid = threadIdx.x;
    int base = blockIdx.x * 128;

    if (tid < 128) {
        int e = base + tid;
        s_tgt[tid] = (e < E) ? ei[e] : 0;
        s_src[tid] = (e < E) ? ei[E + e] : 0;
    }
    __syncthreads();

    int ty = tid >> 4, tx = tid & 15;
    int lr = tid >> 1, lk0 = (tid & 1) * 8;   // A-tile loader
    int wk = tid >> 4, w16 = tid & 15;        // W-tile loader

    // ---------- stage A: H = relu([x_src|x_tgt] @ W1 + b1) ----------
    for (int nh = 0; nh < 2; ++nh) {
        unsigned long long c2[8][4];
        #pragma unroll
        for (int i = 0; i < 8; i++)
            #pragma unroll
            for (int j = 0; j < 4; j++) c2[i][j] = 0ull;

        // preload kt = 0
        {
            int kk = lk0;  // kt=0
            int node = (kk < 128) ? s_src[lr] : s_tgt[lr];
            const float4* p = (const float4*)(x + (size_t)node * DD + (kk & 127));
            float4 a0 = p[0], a1 = p[1];
            const float4* q = (const float4*)(W1 + (size_t)(wk) * HH + nh * 128 + w16 * 8);
            float4 v0 = q[0], v1 = q[1];
            float* Ab = As;
            Ab[(lk0 + 0) * 128 + lr] = a0.x; Ab[(lk0 + 1) * 128 + lr] = a0.y;
            Ab[(lk0 + 2) * 128 + lr] = a0.z; Ab[(lk0 + 3) * 128 + lr] = a0.w;
            Ab[(lk0 + 4) * 128 + lr] = a1.x; Ab[(lk0 + 5) * 128 + lr] = a1.y;
            Ab[(lk0 + 6) * 128 + lr] = a1.z; Ab[(lk0 + 7) * 128 + lr] = a1.w;
            sts_w(Ws, wk, w16, v0, v1);
        }
        __syncthreads();

        for (int kt = 0; kt < 16; ++kt) {
            int cur = kt & 1;
            float4 a0, a1, v0, v1;
            bool pf = (kt + 1 < 16);
            if (pf) {
                int kk = (kt + 1) * 16 + lk0;
                int node = (kk < 128) ? s_src[lr] : s_tgt[lr];
                const float4* p = (const float4*)(x + (size_t)node * DD + (kk & 127));
                a0 = p[0]; a1 = p[1];
                const float4* q = (const float4*)(W1 + (size_t)((kt + 1) * 16 + wk) * HH + nh * 128 + w16 * 8);
                v0 = q[0]; v1 = q[1];
            }
            mma16_f32x2(As + cur * TILE_F, 128, Ws + cur * TILE_F, ty, tx, c2);
            if (pf) {
                float* Ab = As + (cur ^ 1) * TILE_F;
                Ab[(lk0 + 0) * 128 + lr] = a0.x; Ab[(lk0 + 1) * 128 + lr] = a0.y;
                Ab[(lk0 + 2) * 128 + lr] = a0.z; Ab[(lk0 + 3) * 128 + lr] = a0.w;
                Ab[(lk0 + 4) * 128 + lr] = a1.x; Ab[(lk0 + 5) * 128 + lr] = a1.y;
                Ab[(lk0 + 6) * 128 + lr] = a1.z; Ab[(lk0 + 7) * 128 + lr] = a1.w;
                sts_w(Ws + (cur ^ 1) * TILE_F, wk, w16, v0, v1);
            }
            __syncthreads();
        }

        // epilogue: bias + relu -> Ht[n][r]
        #pragma unroll
        for (int j = 0; j < 4; ++j) {
            int n0 = nh * 128 + tx * 8 + 2 * j;
            float bj0 = b1[n0], bj1 = b1[n0 + 1];
            #pragma unroll
            for (int i = 0; i < 8; ++i) {
                float lo, hi; unpack2(c2[i][j], lo, hi);
                Ht[n0 * RP + ty * 8 + i]       = fmaxf(lo + bj0, 0.f);
                Ht[(n0 + 1) * RP + ty * 8 + i] = fmaxf(hi + bj1, 0.f);
            }
        }
        __syncthreads();
    }

    // ---------- stage B: M = H @ W2 + b2 ; scatter-add ----------
    for (int nh = 0; nh < 2; ++nh) {
        unsigned long long c2[8][4];
        #pragma unroll
        for (int i = 0; i < 8; i++)
            #pragma unroll
            for (int j = 0; j < 4; j++) c2[i][j] = 0ull;

        {
            const float4* q = (const float4*)(W2 + (size_t)(wk) * HH + nh * 128 + w16 * 8);
            sts_w(Ws, wk, w16, q[0], q[1]);
        }
        __syncthreads();

        for (int kt = 0; kt < 16; ++kt) {
            int cur = kt & 1;
            float4 v0, v1;
            bool pf = (kt + 1 < 16);
            if (pf) {
                const float4* q = (const float4*)(W2 + (size_t)((kt + 1) * 16 + wk) * HH + nh * 128 + w16 * 8);
                v0 = q[0]; v1 = q[1];
            }
            mma16_f32x2(Ht + kt * 16 * RP, RP, Ws + cur * TILE_F, ty, tx, c2);
            if (pf) sts_w(Ws + (cur ^ 1) * TILE_F, wk, w16, v0, v1);
            __syncthreads();
        }

        // epilogue: scatter-add into messages[tgt]
        #pragma unroll
        for (int i = 0; i < 8; i++) {
            int r = ty * 8 + i;
            if (base + r < E) {
                int node = s_tgt[r];
                float* mrow = messages + (size_t)node * HH + nh * 128 + tx * 8;
                #pragma unroll
                for (int j = 0; j < 4; j++) {
                    float lo, hi; unpack2(c2[i][j], lo, hi);
                    atomicAdd(mrow + 2 * j,     lo + b2[nh * 128 + tx * 8 + 2 * j]);
                    atomicAdd(mrow + 2 * j + 1, hi + b2[nh * 128 + tx * 8 + 2 * j + 1]);
                }
            }
        }
        __syncthreads();
    }
}

// ---------------- block-diagonal cross attention ----------------
__global__ void attn_kernel(const float* __restrict__ x1,
                            const float* __restrict__ x2, int N) {
    int b = blockIdx.x;
    int dir = blockIdx.y;
    const float* rowsrc = dir ? x2 : x1;
    const float* colsrc = dir ? x1 : x2;
    float* att = g_att + (size_t)dir * N * DD;
    int rs = g_seg[(dir * NB + b) * 2 + 0];
    int re = g_seg[(dir * NB + b) * 2 + 1];
    int cs = g_seg[((1 - dir) * NB + b) * 2 + 0];
    int ce = g_seg[((1 - dir) * NB + b) * 2 + 1];
    const float* mean = g_colmeans + (1 - dir) * DD;

    int warp = threadIdx.x >> 5, lane = threadIdx.x & 31;

    for (int i = rs + warp; i < re; i += 8) {
        float4 a = *(const float4*)(rowsrc + (size_t)i * DD + lane * 4);
        float4 res;
        if (cs == ce) {
            float4 mv = *(const float4*)(mean + lane * 4);
            res.x = a.x - mv.x; res.y = a.y - mv.y;
            res.z = a.z - mv.z; res.w = a.w - mv.w;
        } else {
            float m = -3.4e38f;
            for (int j = cs; j < ce; ++j) {
                float4 bv = *(const float4*)(colsrc + (size_t)j * DD + lane * 4);
                float d = a.x * bv.x + a.y * bv.y + a.z * bv.z + a.w * bv.w;
                #pragma unroll
                for (int o = 16; o; o >>= 1) d += __shfl_xor_sync(0xffffffffu, d, o);
                m = fmaxf(m, d);
            }
            float se = 0.f;
            float4 acc = make_float4(0.f, 0.f, 0.f, 0.f);
            for (int j = cs; j < ce; ++j) {
                float4 bv = *(const float4*)(colsrc + (size_t)j * DD + lane * 4);
                float d = a.x * bv.x + a.y * bv.y + a.z * bv.z + a.w * bv.w;
                #pragma unroll
                for (int o = 16; o; o >>= 1) d += __shfl_xor_sync(0xffffffffu, d, o);
                float w = __expf(d - m);
                se += w;
                acc.x = fmaf(w, bv.x, acc.x);
                acc.y = fmaf(w, bv.y, acc.y);
                acc.z = fmaf(w, bv.z, acc.z);
                acc.w = fmaf(w, bv.w, acc.w);
            }
            float inv = 1.f / se;
            res.x = a.x - acc.x * inv; res.y = a.y - acc.y * inv;
            res.z = a.z - acc.z * inv; res.w = a.w - acc.w * inv;
        }
        *(float4*)(att + (size_t)i * DD + lane * 4) = res;
    }
}

// ---------------- fused node update MLP ----------------
__global__ void __launch_bounds__(256, 1)
upd_kernel(const float* __restrict__ x1, const float* __restrict__ x2,
           const float* __restrict__ W1u, const float* __restrict__ b1u,
           const float* __restrict__ W2u, const float* __restrict__ b2u,
           float* __restrict__ out, int N) {
    int g = blockIdx.y;
    const float* x = g ? x2 : x1;
    const float* messages = g_messages + (size_t)g * N * HH;
    const float* att = g_att + (size_t)g * N * DD;
    float* o = out + (size_t)g * N * DD;

    extern __shared__ float sm[];
    float* Ht = sm;
    float* As = Ht + 256 * RP;
    float* Ws = As + 2 * TILE_F;

    int tid = threadIdx.x;
    int base = blockIdx.x * 128;
    int ty = tid >> 4, tx = tid & 15;
    int lr = tid >> 1, lk0 = (tid & 1) * 8;
    int wk = tid >> 4, w16 = tid & 15;

    int mynode = base + lr;
    if (mynode >= N) mynode = N - 1;
    const float* rowm = messages + (size_t)mynode * HH;
    const float* rowa = att + (size_t)mynode * DD;
    const float* rowx = x + (size_t)mynode * DD;

    // ---------- stage 1: K = 512, u = [msg|att|x] ----------
    for (int nh = 0; nh < 2; ++nh) {
        unsigned long long c2[8][4];
        #pragma unroll
        for (int i = 0; i < 8; i++)
            #pragma unroll
            for (int j = 0; j < 4; j++) c2[i][j] = 0ull;

        {
            int kk = lk0;
            const float4* p = (const float4*)(rowm + kk);   // kt=0 -> messages
            float4 a0 = p[0], a1 = p[1];
            const float4* q = (const float4*)(W1u + (size_t)(wk) * HH + nh * 128 + w16 * 8);
            float4 v0 = q[0], v1 = q[1];
            float* Ab = As;
            Ab[(lk0 + 0) * 128 + lr] = a0.x; Ab[(lk0 + 1) * 128 + lr] = a0.y;
            Ab[(lk0 + 2) * 128 + lr] = a0.z; Ab[(lk0 + 3) * 128 + lr] = a0.w;
            Ab[(lk0 + 4) * 128 + lr] = a1.x; Ab[(lk0 + 5) * 128 + lr] = a1.y;
            Ab[(lk0 + 6) * 128 + lr] = a1.z; Ab[(lk0 + 7) * 128 + lr] = a1.w;
            sts_w(Ws, wk, w16, v0, v1);
        }
        __syncthreads();

        for (int kt = 0; kt < 32; ++kt) {
            int cur = kt & 1;
            float4 a0, a1, v0, v1;
            bool pf = (kt + 1 < 32);
            if (pf) {
                int kk = (kt + 1) * 16 + lk0;
                const float* src;
                int col;
                if (kk < 256)      { src = rowm; col = kk; }
                else if (kk < 384) { src = rowa; col = kk - 256; }
                else               { src = rowx; col = kk - 384; }
                const float4* p = (const float4*)(src + col);
                a0 = p[0]; a1 = p[1];
                const float4* q = (const float4*)(W1u + (size_t)((kt + 1) * 16 + wk) * HH + nh * 128 + w16 * 8);
                v0 = q[0]; v1 = q[1];
            }
            mma16_f32x2(As + cur * TILE_F, 128, Ws + cur * TILE_F, ty, tx, c2);
            if (pf) {
                float* Ab = As + (cur ^ 1) * TILE_F;
                Ab[(lk0 + 0) * 128 + lr] = a0.x; Ab[(lk0 + 1) * 128 + lr] = a0.y;
                Ab[(lk0 + 2) * 128 + lr] = a0.z; Ab[(lk0 + 3) * 128 + lr] = a0.w;
                Ab[(lk0 + 4) * 128 + lr] = a1.x; Ab[(lk0 + 5) * 128 + lr] = a1.y;
                Ab[(lk0 + 6) * 128 + lr] = a1.z; Ab[(lk0 + 7) * 128 + lr] = a1.w;
                sts_w(Ws + (cur ^ 1) * TILE_F, wk, w16, v0, v1);
            }
            __syncthreads();
        }

        #pragma unroll
        for (int j = 0; j < 4; ++j) {
            int n0 = nh * 128 + tx * 8 + 2 * j;
            float bj0 = b1u[n0], bj1 = b1u[n0 + 1];
            #pragma unroll
            for (int i = 0; i < 8; ++i) {
                float lo, hi; unpack2(c2[i][j], lo, hi);
                Ht[n0 * RP + ty * 8 + i]       = fmaxf(lo + bj0, 0.f);
                Ht[(n0 + 1) * RP + ty * 8 + i] = fmaxf(hi + bj1, 0.f);
            }
        }
        __syncthreads();
    }

    // ---------- stage 2: out = x + Ht(128x256) @ W2u(256x128) + b2u ----------
    {
        unsigned long long c2[8][4];
        #pragma unroll
        for (int i = 0; i < 8; i++)
            #pragma unroll
            for (int j = 0; j < 4; j++) c2[i][j] = 0ull;

        {
            const float4* q = (const float4*)(W2u + (size_t)(wk) * DD + w16 * 8);
            sts_w(Ws, wk, w16, q[0], q[1]);
        }
        __syncthreads();

        for (int kt = 0; kt < 16; ++kt) {
            int cur = kt & 1;
            float4 v0, v1;
            bool pf = (kt + 1 < 16);
            if (pf) {
                const float4* q = (const float4*)(W2u + (size_t)((kt + 1) * 16 + wk) * DD + w16 * 8);
                v0 = q[0]; v1 = q[1];
            }
            mma16_f32x2(Ht + kt * 16 * RP, RP, Ws + cur * TILE_F, ty, tx, c2);
            if (pf) sts_w(Ws + (cur ^ 1) * TILE_F, wk, w16, v0, v1);
            __syncthreads();
        }

        #pragma unroll
        for (int i = 0; i < 8; i++) {
            int node = base + ty * 8 + i;
            if (node < N) {
                int col = tx * 8;
                #pragma unroll
                for (int j = 0; j < 4; j++) {
                    float lo, hi; unpack2(c2[i][j], lo, hi);
                    float r0 = lo + b2u[col + 2 * j]     + x[(size_t)node * DD + col + 2 * j];
                    float r1 = hi + b2u[col + 2 * j + 1] + x[(size_t)node * DD + col + 2 * j + 1];
                    o[(size_t)node * DD + col + 2 * j]     = r0;
                    o[(size_t)node * DD + col + 2 * j + 1] = r1;
                }
            }
        }
    }
}

// ---------------- launcher ----------------
extern "C" void kernel_launch(void* const* d_in, const int* in_sizes, int n_in,
                              void* d_out, int out_size) {
    const float* x1   = (const float*)d_in[0];
    const int*   ei1  = (const int*)d_in[1];
    const int*   bat1 = (const int*)d_in[2];
    const float* x2   = (const float*)d_in[3];
    const int*   ei2  = (const int*)d_in[4];
    const int*   bat2 = (const int*)d_in[5];
    const float* mW1 = (const float*)d_in[6];
    const float* mb1 = (const float*)d_in[7];
    const float* mW2 = (const float*)d_in[8];
    const float* mb2 = (const float*)d_in[9];
    const float* uW1 = (const float*)d_in[10];
    const float* ub1 = (const float*)d_in[11];
    const float* uW2 = (const float*)d_in[12];
    const float* ub2 = (const float*)d_in[13];
    float* out = (float*)d_out;

    int N = in_sizes[2];          // nodes per graph
    int E = in_sizes[1] / 2;      // edges per graph

    cudaFuncSetAttribute(msg_kernel, cudaFuncAttributeMaxDynamicSharedMemorySize, SMEM_BYTES);
    cudaFuncSetAttribute(upd_kernel, cudaFuncAttributeMaxDynamicSharedMemorySize, SMEM_BYTES);

    int zn = 2 * N * HH;
    zero_msgs_kernel<<<(zn + 255) / 256, 256>>>(zn);
    seg_kernel<<<1, 128>>>(bat1, bat2, N);
    colmean_kernel<<<2, DD>>>(x1, x2, N);

    dim3 mgrid((E + 127) / 128, 2);
    msg_kernel<<<mgrid, 256, SMEM_BYTES>>>(x1, x2, ei1, ei2, mW1, mb1, mW2, mb2, N, E);

    attn_kernel<<<dim3(NB, 2), 256>>>(x1, x2, N);

    dim3 ugrid((N + 127) / 128, 2);
    upd_kernel<<<ugrid, 256, SMEM_BYTES>>>(x1, x2, uW1, ub1, uW2, ub2, out, N);
}

// round 4
// speedup vs baseline: 1.2088x; 1.1042x over previous
#include <cuda_runtime.h>
#include <cuda_bf16.h>
#include <math.h>

// ---------------- problem constants ----------------
#define DD      128      // node feature dim
#define HH      256      // hidden = 2*D
#define MAXN    8192
#define NB      64       // batches
#define RP      132      // padded row stride for Ht (256 x 132 floats)

// scratch (global __device__ arrays: sanctioned, no cudaMalloc)
__device__ float g_messages[2ull * MAXN * HH];   // 16 MB
__device__ float g_att[2ull * MAXN * DD];        // 8 MB
__device__ float g_colmeans[2 * DD];
__device__ int   g_seg[2 * NB * 2];

// shared memory layout for the fused MLP kernels:
// Ht: 256*RP floats, As: 2 x 16*128, Ws: 2 x 16*128, ids: 256 ints
#define TILE_F   (16*128)
#define SMEM_FLOATS (256*RP + 2*TILE_F + 2*TILE_F)
#define SMEM_BYTES  (SMEM_FLOATS*4 + 256*4)

// ---------------- async copy helpers ----------------
__device__ __forceinline__ void cp_async16(unsigned int saddr, const void* gptr) {
    asm volatile("cp.async.cg.shared.global [%0], [%1], 16;" :: "r"(saddr), "l"(gptr));
}
__device__ __forceinline__ void cp_commit() {
    asm volatile("cp.async.commit_group;");
}
__device__ __forceinline__ void cp_wait0() {
    asm volatile("cp.async.wait_group 0;");
}
__device__ __forceinline__ void red_add_v4(float* p, float a, float b, float c, float d) {
    asm volatile("red.global.add.v4.f32 [%0], {%1,%2,%3,%4};"
                 :: "l"(p), "f"(a), "f"(b), "f"(c), "f"(d) : "memory");
}

// ---------------- tiny setup kernels ----------------
__global__ void zero_msgs_kernel(int n4) {
    int i = blockIdx.x * blockDim.x + threadIdx.x;
    if (i < n4) ((float4*)g_messages)[i] = make_float4(0.f, 0.f, 0.f, 0.f);
}

__global__ void seg_kernel(const int* __restrict__ b1,
                           const int* __restrict__ b2, int N) {
    int t = threadIdx.x;
    if (t >= 2 * NB) return;
    int g = t / NB;
    int b = t % NB;
    const int* arr = g ? b2 : b1;
    int lo = 0, hi = N;
    while (lo < hi) { int mid = (lo + hi) >> 1; if (arr[mid] < b) lo = mid + 1; else hi = mid; }
    int start = lo;
    lo = 0; hi = N;
    while (lo < hi) { int mid = (lo + hi) >> 1; if (arr[mid] <= b) lo = mid + 1; else hi = mid; }
    g_seg[t * 2 + 0] = start;
    g_seg[t * 2 + 1] = lo;
}

__global__ void colmean_kernel(const float* __restrict__ x1,
                               const float* __restrict__ x2, int N) {
    const float* x = blockIdx.x ? x2 : x1;
    int c = threadIdx.x;   // 0..127
    float s0 = 0.f, s1 = 0.f, s2 = 0.f, s3 = 0.f;
    int r = 0;
    for (; r + 3 < N; r += 4) {
        s0 += x[(size_t)(r + 0) * DD + c];
        s1 += x[(size_t)(r + 1) * DD + c];
        s2 += x[(size_t)(r + 2) * DD + c];
        s3 += x[(size_t)(r + 3) * DD + c];
    }
    for (; r < N; ++r) s0 += x[(size_t)r * DD + c];
    g_colmeans[blockIdx.x * DD + c] = (s0 + s1 + s2 + s3) * (1.f / (float)N);
}

// ---------------- f32x2 micro-kernel ----------------
// A tile: [16][astride] k-major
// W tile: [16][128] split-half layout: Wtile[k*128 + h*64 + tx*4 + q]
//         holds original col (tx*8 + h*4 + q) -> thread tx owns cols tx*8..+7
// c2[i][j] accumulates packed (cols 2j, 2j+1) of this thread's 8-col block
__device__ __forceinline__ void mma16_f32x2(
    const float* __restrict__ Atile, int astride,
    const float* __restrict__ Wtile,
    int ty, int tx, unsigned long long c2[8][4])
{
    #pragma unroll
    for (int k = 0; k < 16; ++k) {
        float4 t0 = *(const float4*)(Atile + k * astride + ty * 8);
        float4 t1 = *(const float4*)(Atile + k * astride + ty * 8 + 4);
        ulonglong2 u0 = *(const ulonglong2*)(Wtile + k * 128 + tx * 4);
        ulonglong2 u1 = *(const ulonglong2*)(Wtile + k * 128 + 64 + tx * 4);
        unsigned long long b2[4];
        b2[0] = u0.x; b2[1] = u0.y; b2[2] = u1.x; b2[3] = u1.y;
        unsigned int ar[8];
        ar[0]=__float_as_uint(t0.x); ar[1]=__float_as_uint(t0.y);
        ar[2]=__float_as_uint(t0.z); ar[3]=__float_as_uint(t0.w);
        ar[4]=__float_as_uint(t1.x); ar[5]=__float_as_uint(t1.y);
        ar[6]=__float_as_uint(t1.z); ar[7]=__float_as_uint(t1.w);
        unsigned long long a2[8];
        #pragma unroll
        for (int i = 0; i < 8; i++)
            asm("mov.b64 %0, {%1, %1};" : "=l"(a2[i]) : "r"(ar[i]));
        #pragma unroll
        for (int i = 0; i < 8; i++)
            #pragma unroll
            for (int j = 0; j < 4; j++)
                asm("fma.rn.f32x2 %0, %1, %2, %0;"
                    : "+l"(c2[i][j]) : "l"(a2[i]), "l"(b2[j]));
    }
}

__device__ __forceinline__ void unpack2(unsigned long long v, float& lo, float& hi) {
    unsigned int l, h;
    asm("mov.b64 {%0, %1}, %2;" : "=r"(l), "=r"(h) : "l"(v));
    lo = __uint_as_float(l); hi = __uint_as_float(h);
}

// issue cp.async for one W tile row-fragment into split layout
__device__ __forceinline__ void cp_w(unsigned int ws_saddr, int buf, int wk, int w16,
                                     const float* __restrict__ wrow) {
    unsigned int base = ws_saddr + (unsigned int)((buf * TILE_F + wk * 128 + w16 * 4) * 4);
    cp_async16(base,           wrow + w16 * 8);
    cp_async16(base + 64 * 4,  wrow + w16 * 8 + 4);
}

// scatter 8 A values (k-major transpose) into tile
__device__ __forceinline__ void sts_a(float* Ab, int lk0, int lr, float4 a0, float4 a1) {
    Ab[(lk0 + 0) * 128 + lr] = a0.x; Ab[(lk0 + 1) * 128 + lr] = a0.y;
    Ab[(lk0 + 2) * 128 + lr] = a0.z; Ab[(lk0 + 3) * 128 + lr] = a0.w;
    Ab[(lk0 + 4) * 128 + lr] = a1.x; Ab[(lk0 + 5) * 128 + lr] = a1.y;
    Ab[(lk0 + 6) * 128 + lr] = a1.z; Ab[(lk0 + 7) * 128 + lr] = a1.w;
}

// ---------------- fused message MLP + scatter ----------------
__global__ void __launch_bounds__(256, 1)
msg_kernel(const float* __restrict__ x1, const float* __restrict__ x2,
           const int* __restrict__ ei1, const int* __restrict__ ei2,
           const float* __restrict__ W1, const float* __restrict__ b1,
           const float* __restrict__ W2, const float* __restrict__ b2,
           int N, int E) {
    int g = blockIdx.y;
    const float* x = g ? x2 : x1;
    const int* ei = g ? ei2 : ei1;
    float* messages = g_messages + (size_t)g * N * HH;

    extern __shared__ float sm[];
    float* Ht = sm;                        // [256][RP]
    float* As = Ht + 256 * RP;             // [2][16*128]
    float* Ws = As + 2 * TILE_F;           // [2][16*128]
    int*   s_src = (int*)(Ws + 2 * TILE_F);
    int*   s_tgt = s_src + 128;
    unsigned int ws_saddr = (unsigned int)__cvta_generic_to_shared(Ws);

    int tid = threadIdx.x;
    int base = blockIdx.x * 128;

    if (tid < 128) {
        int e = base + tid;
        s_tgt[tid] = (e < E) ? ei[e] : 0;
        s_src[tid] = (e < E) ? ei[E + e] : 0;
    }
    __syncthreads();

    int ty = tid >> 4, tx = tid & 15;
    int lr = tid >> 1, lk0 = (tid & 1) * 8;   // A-tile loader
    int wk = tid >> 4, w16 = tid & 15;        // W-tile loader

    // ---------- stage A: H = relu([x_src|x_tgt] @ W1 + b1) ----------
    for (int nh = 0; nh < 2; ++nh) {
        unsigned long long c2[8][4];
        #pragma unroll
        for (int i = 0; i < 8; i++)
            #pragma unroll
            for (int j = 0; j < 4; j++) c2[i][j] = 0ull;

        // preload kt = 0
        {
            cp_w(ws_saddr, 0, wk, w16, W1 + (size_t)wk * HH + nh * 128);
            cp_commit();
            int kk = lk0;
            int node = (kk < 128) ? s_src[lr] : s_tgt[lr];
            const float4* p = (const float4*)(x + (size_t)node * DD + (kk & 127));
            sts_a(As, lk0, lr, p[0], p[1]);
            cp_wait0();
        }
        __syncthreads();

        for (int kt = 0; kt < 16; ++kt) {
            int cur = kt & 1;
            float4 a0, a1;
            bool pf = (kt + 1 < 16);
            if (pf) {
                int kk = (kt + 1) * 16 + lk0;
                int node = (kk < 128) ? s_src[lr] : s_tgt[lr];
                const float4* p = (const float4*)(x + (size_t)node * DD + (kk & 127));
                a0 = p[0]; a1 = p[1];
                cp_w(ws_saddr, cur ^ 1, wk, w16,
                     W1 + (size_t)((kt + 1) * 16 + wk) * HH + nh * 128);
                cp_commit();
            }
            mma16_f32x2(As + cur * TILE_F, 128, Ws + cur * TILE_F, ty, tx, c2);
            if (pf) sts_a(As + (cur ^ 1) * TILE_F, lk0, lr, a0, a1);
            cp_wait0();
            __syncthreads();
        }

        // epilogue: bias + relu -> Ht[n][r]
        #pragma unroll
        for (int j = 0; j < 4; ++j) {
            int n0 = nh * 128 + tx * 8 + 2 * j;
            float bj0 = b1[n0], bj1 = b1[n0 + 1];
            #pragma unroll
            for (int i = 0; i < 8; ++i) {
                float lo, hi; unpack2(c2[i][j], lo, hi);
                Ht[n0 * RP + ty * 8 + i]       = fmaxf(lo + bj0, 0.f);
                Ht[(n0 + 1) * RP + ty * 8 + i] = fmaxf(hi + bj1, 0.f);
            }
        }
        __syncthreads();
    }

    // ---------- stage B: M = H @ W2 + b2 ; scatter-add ----------
    for (int nh = 0; nh < 2; ++nh) {
        unsigned long long c2[8][4];
        #pragma unroll
        for (int i = 0; i < 8; i++)
            #pragma unroll
            for (int j = 0; j < 4; j++) c2[i][j] = 0ull;

        cp_w(ws_saddr, 0, wk, w16, W2 + (size_t)wk * HH + nh * 128);
        cp_commit();
        cp_wait0();
        __syncthreads();

        for (int kt = 0; kt < 16; ++kt) {
            int cur = kt & 1;
            bool pf = (kt + 1 < 16);
            if (pf) {
                cp_w(ws_saddr, cur ^ 1, wk, w16,
                     W2 + (size_t)((kt + 1) * 16 + wk) * HH + nh * 128);
                cp_commit();
            }
            mma16_f32x2(Ht + kt * 16 * RP, RP, Ws + cur * TILE_F, ty, tx, c2);
            cp_wait0();
            __syncthreads();
        }

        // epilogue: vectorized scatter-add into messages[tgt]
        float bb[8];
        #pragma unroll
        for (int q = 0; q < 8; q++) bb[q] = b2[nh * 128 + tx * 8 + q];
        #pragma unroll
        for (int i = 0; i < 8; i++) {
            int r = ty * 8 + i;
            if (base + r < E) {
                int node = s_tgt[r];
                float* mrow = messages + (size_t)node * HH + nh * 128 + tx * 8;
                float v[8];
                #pragma unroll
                for (int j = 0; j < 4; j++) {
                    float lo, hi; unpack2(c2[i][j], lo, hi);
                    v[2 * j] = lo + bb[2 * j];
                    v[2 * j + 1] = hi + bb[2 * j + 1];
                }
                red_add_v4(mrow,     v[0], v[1], v[2], v[3]);
                red_add_v4(mrow + 4, v[4], v[5], v[6], v[7]);
            }
        }
        __syncthreads();
    }
}

// ---------------- block-diagonal cross attention ----------------
__global__ void attn_kernel(const float* __restrict__ x1,
                            const float* __restrict__ x2, int N) {
    int b = blockIdx.x;
    int dir = blockIdx.y;
    const float* rowsrc = dir ? x2 : x1;
    const float* colsrc = dir ? x1 : x2;
    float* att = g_att + (size_t)dir * N * DD;
    int rs = g_seg[(dir * NB + b) * 2 + 0];
    int re = g_seg[(dir * NB + b) * 2 + 1];
    int cs = g_seg[((1 - dir) * NB + b) * 2 + 0];
    int ce = g_seg[((1 - dir) * NB + b) * 2 + 1];
    const float* mean = g_colmeans + (1 - dir) * DD;

    int warp = threadIdx.x >> 5, lane = threadIdx.x & 31;

    for (int i = rs + warp; i < re; i += 8) {
        float4 a = *(const float4*)(rowsrc + (size_t)i * DD + lane * 4);
        float4 res;
        if (cs == ce) {
            float4 mv = *(const float4*)(mean + lane * 4);
            res.x = a.x - mv.x; res.y = a.y - mv.y;
            res.z = a.z - mv.z; res.w = a.w - mv.w;
        } else {
            float m = -3.4e38f;
            for (int j = cs; j < ce; ++j) {
                float4 bv = *(const float4*)(colsrc + (size_t)j * DD + lane * 4);
                float d = a.x * bv.x + a.y * bv.y + a.z * bv.z + a.w * bv.w;
                #pragma unroll
                for (int o = 16; o; o >>= 1) d += __shfl_xor_sync(0xffffffffu, d, o);
                m = fmaxf(m, d);
            }
            float se = 0.f;
            float4 acc = make_float4(0.f, 0.f, 0.f, 0.f);
            for (int j = cs; j < ce; ++j) {
                float4 bv = *(const float4*)(colsrc + (size_t)j * DD + lane * 4);
                float d = a.x * bv.x + a.y * bv.y + a.z * bv.z + a.w * bv.w;
                #pragma unroll
                for (int o = 16; o; o >>= 1) d += __shfl_xor_sync(0xffffffffu, d, o);
                float w = __expf(d - m);
                se += w;
                acc.x = fmaf(w, bv.x, acc.x);
                acc.y = fmaf(w, bv.y, acc.y);
                acc.z = fmaf(w, bv.z, acc.z);
                acc.w = fmaf(w, bv.w, acc.w);
            }
            float inv = 1.f / se;
            res.x = a.x - acc.x * inv; res.y = a.y - acc.y * inv;
            res.z = a.z - acc.z * inv; res.w = a.w - acc.w * inv;
        }
        *(float4*)(att + (size_t)i * DD + lane * 4) = res;
    }
}

// ---------------- fused node update MLP ----------------
__global__ void __launch_bounds__(256, 1)
upd_kernel(const float* __restrict__ x1, const float* __restrict__ x2,
           const float* __restrict__ W1u, const float* __restrict__ b1u,
           const float* __restrict__ W2u, const float* __restrict__ b2u,
           float* __restrict__ out, int N) {
    int g = blockIdx.y;
    const float* x = g ? x2 : x1;
    const float* messages = g_messages + (size_t)g * N * HH;
    const float* att = g_att + (size_t)g * N * DD;
    float* o = out + (size_t)g * N * DD;

    extern __shared__ float sm[];
    float* Ht = sm;
    float* As = Ht + 256 * RP;
    float* Ws = As + 2 * TILE_F;
    unsigned int ws_saddr = (unsigned int)__cvta_generic_to_shared(Ws);

    int tid = threadIdx.x;
    int base = blockIdx.x * 128;
    int ty = tid >> 4, tx = tid & 15;
    int lr = tid >> 1, lk0 = (tid & 1) * 8;
    int wk = tid >> 4, w16 = tid & 15;

    int mynode = base + lr;
    if (mynode >= N) mynode = N - 1;
    const float* rowm = messages + (size_t)mynode * HH;
    const float* rowa = att + (size_t)mynode * DD;
    const float* rowx = x + (size_t)mynode * DD;

    // ---------- stage 1: K = 512, u = [msg|att|x] ----------
    for (int nh = 0; nh < 2; ++nh) {
        unsigned long long c2[8][4];
        #pragma unroll
        for (int i = 0; i < 8; i++)
            #pragma unroll
            for (int j = 0; j < 4; j++) c2[i][j] = 0ull;

        {
            cp_w(ws_saddr, 0, wk, w16, W1u + (size_t)wk * HH + nh * 128);
            cp_commit();
            const float4* p = (const float4*)(rowm + lk0);   // kt=0 -> messages
            sts_a(As, lk0, lr, p[0], p[1]);
            cp_wait0();
        }
        __syncthreads();

        for (int kt = 0; kt < 32; ++kt) {
            int cur = kt & 1;
            float4 a0, a1;
            bool pf = (kt + 1 < 32);
            if (pf) {
                int kk = (kt + 1) * 16 + lk0;
                const float* src;
                int col;
                if (kk < 256)      { src = rowm; col = kk; }
                else if (kk < 384) { src = rowa; col = kk - 256; }
                else               { src = rowx; col = kk - 384; }
                const float4* p = (const float4*)(src + col);
                a0 = p[0]; a1 = p[1];
                cp_w(ws_saddr, cur ^ 1, wk, w16,
                     W1u + (size_t)((kt + 1) * 16 + wk) * HH + nh * 128);
                cp_commit();
            }
            mma16_f32x2(As + cur * TILE_F, 128, Ws + cur * TILE_F, ty, tx, c2);
            if (pf) sts_a(As + (cur ^ 1) * TILE_F, lk0, lr, a0, a1);
            cp_wait0();
            __syncthreads();
        }

        #pragma unroll
        for (int j = 0; j < 4; ++j) {
            int n0 = nh * 128 + tx * 8 + 2 * j;
            float bj0 = b1u[n0], bj1 = b1u[n0 + 1];
            #pragma unroll
            for (int i = 0; i < 8; ++i) {
                float lo, hi; unpack2(c2[i][j], lo, hi);
                Ht[n0 * RP + ty * 8 + i]       = fmaxf(lo + bj0, 0.f);
                Ht[(n0 + 1) * RP + ty * 8 + i] = fmaxf(hi + bj1, 0.f);
            }
        }
        __syncthreads();
    }

    // ---------- stage 2: out = x + Ht(128x256) @ W2u(256x128) + b2u ----------
    {
        unsigned long long c2[8][4];
        #pragma unroll
        for (int i = 0; i < 8; i++)
            #pragma unroll
            for (int j = 0; j < 4; j++) c2[i][j] = 0ull;

        cp_w(ws_saddr, 0, wk, w16, W2u + (size_t)wk * DD);
        cp_commit();
        cp_wait0();
        __syncthreads();

        for (int kt = 0; kt < 16; ++kt) {
            int cur = kt & 1;
            bool pf = (kt + 1 < 16);
            if (pf) {
                cp_w(ws_saddr, cur ^ 1, wk, w16, W2u + (size_t)((kt + 1) * 16 + wk) * DD);
                cp_commit();
            }
            mma16_f32x2(Ht + kt * 16 * RP, RP, Ws + cur * TILE_F, ty, tx, c2);
            cp_wait0();
            __syncthreads();
        }

        #pragma unroll
        for (int i = 0; i < 8; i++) {
            int node = base + ty * 8 + i;
            if (node < N) {
                int col = tx * 8;
                float4 r0, r1;
                float lo, hi;
                unpack2(c2[i][0], lo, hi);
                r0.x = lo + b2u[col + 0] + x[(size_t)node * DD + col + 0];
                r0.y = hi + b2u[col + 1] + x[(size_t)node * DD + col + 1];
                unpack2(c2[i][1], lo, hi);
                r0.z = lo + b2u[col + 2] + x[(size_t)node * DD + col + 2];
                r0.w = hi + b2u[col + 3] + x[(size_t)node * DD + col + 3];
                unpack2(c2[i][2], lo, hi);
                r1.x = lo + b2u[col + 4] + x[(size_t)node * DD + col + 4];
                r1.y = hi + b2u[col + 5] + x[(size_t)node * DD + col + 5];
                unpack2(c2[i][3], lo, hi);
                r1.z = lo + b2u[col + 6] + x[(size_t)node * DD + col + 6];
                r1.w = hi + b2u[col + 7] + x[(size_t)node * DD + col + 7];
                *(float4*)(o + (size_t)node * DD + col) = r0;
                *(float4*)(o + (size_t)node * DD + col + 4) = r1;
            }
        }
    }
}

// ---------------- launcher ----------------
extern "C" void kernel_launch(void* const* d_in, const int* in_sizes, int n_in,
                              void* d_out, int out_size) {
    const float* x1   = (const float*)d_in[0];
    const int*   ei1  = (const int*)d_in[1];
    const int*   bat1 = (const int*)d_in[2];
    const float* x2   = (const float*)d_in[3];
    const int*   ei2  = (const int*)d_in[4];
    const int*   bat2 = (const int*)d_in[5];
    const float* mW1 = (const float*)d_in[6];
    const float* mb1 = (const float*)d_in[7];
    const float* mW2 = (const float*)d_in[8];
    const float* mb2 = (const float*)d_in[9];
    const float* uW1 = (const float*)d_in[10];
    const float* ub1 = (const float*)d_in[11];
    const float* uW2 = (const float*)d_in[12];
    const float* ub2 = (const float*)d_in[13];
    float* out = (float*)d_out;

    int N = in_sizes[2];          // nodes per graph
    int E = in_sizes[1] / 2;      // edges per graph

    cudaFuncSetAttribute(msg_kernel, cudaFuncAttributeMaxDynamicSharedMemorySize, SMEM_BYTES);
    cudaFuncSetAttribute(upd_kernel, cudaFuncAttributeMaxDynamicSharedMemorySize, SMEM_BYTES);

    int zn4 = 2 * N * HH / 4;
    zero_msgs_kernel<<<(zn4 + 255) / 256, 256>>>(zn4);
    seg_kernel<<<1, 128>>>(bat1, bat2, N);
    colmean_kernel<<<2, DD>>>(x1, x2, N);

    dim3 mgrid((E + 127) / 128, 2);
    msg_kernel<<<mgrid, 256, SMEM_BYTES>>>(x1, x2, ei1, ei2, mW1, mb1, mW2, mb2, N, E);

    attn_kernel<<<dim3(NB, 2), 256>>>(x1, x2, N);

    dim3 ugrid((N + 127) / 128, 2);
    upd_kernel<<<ugrid, 256, SMEM_BYTES>>>(x1, x2, uW1, ub1, uW2, ub2, out, N);
}